// round 15
// baseline (speedup 1.0000x reference)
#include <cuda_runtime.h>
#include <cstdint>

// Tucker via time-bucketing, round 15: three kernels.
//   scatter : slot-scatter by k (int4 slots, CAP=96, overflow fallback)
//   build_w : W_k = C x_r t_k  (C in SMEM float4-q layout, G=2, f32x2 math,
//             SMEM-transpose then coalesced STG to g_W)
//   sample  : lane = sample, 2 CTAs x 512 thr per SM (32 warps). Per bucket:
//             8 coalesced LDG of W -> per-warp SMEM; then 25-issue/sample
//             loop (uniform LDS.128 W broadcasts + f32x2).

#define NTIME       5000
#define NUM_CTAS    148
#define CAP         96

// ---- device scratch (zero-init at load) ----
__device__ int4  g_slot[NTIME * CAP];     // (idx, iu, ij, 0)
__device__ float g_W[NTIME * 1024];       // [b][p][q]
__device__ int   g_counts[NTIME];
__device__ int   g_ovf[4096];
__device__ int   g_ovf_cnt;
__device__ int   g_ticket_w;
__device__ int   g_ticket_s;

// ---- packed f32x2 helpers ----
#define PACK2(d, lo, hi) asm("mov.b64 %0, {%1, %2};" : "=l"(d) : "f"(lo), "f"(hi))
#define UNPACK2(lo, hi, s) asm("mov.b64 {%0, %1}, %2;" : "=f"(lo), "=f"(hi) : "l"(s))
#define FMA2(acc, a, b) asm("fma.rn.f32x2 %0, %1, %2, %0;" : "+l"(acc) : "l"(a), "l"(b))
#define LDSV2U64(d0, d1, addr) \
    asm volatile("ld.shared.v2.u64 {%0, %1}, [%2];" : "=l"(d0), "=l"(d1) : "r"(addr))

__device__ __forceinline__ uint32_t smem_u32(const void* p) {
    uint32_t a;
    asm("{ .reg .u64 t; cvta.to.shared.u64 t, %1; cvt.u32.u64 %0, t; }" : "=r"(a) : "l"(p));
    return a;
}

// ============================ scatter ============================
__global__ void scatter_kernel(const int* __restrict__ k_in,
                               const int* __restrict__ i_in,
                               const int* __restrict__ j_in, int n) {
    int x = blockIdx.x * blockDim.x + threadIdx.x;
    if (x == 0) { g_ticket_w = 0; g_ticket_s = 0; }
    if (x < n) {
        int k  = k_in[x];
        int iu = i_in[x];
        int ij = j_in[x];
        int pos = atomicAdd(&g_counts[k], 1);
        if (pos < CAP) {
            g_slot[k * CAP + pos] = make_int4(x, iu, ij, 0);
        } else {
            int o = atomicAdd(&g_ovf_cnt, 1);
            if (o < 4096) g_ovf[o] = x;
        }
    }
}

// ============================ build_w ============================
// SMEM (floats):
//   [0, 32768)        C as float4 q-quads: Cs4[(r*8 + q4)*32 + p] =
//                     {C[p][4q4..4q4+3][r]}   (16B/lane stride: conflict-free)
//   per warp:         32768 + wid*1152 : transpose buffer Wtr[p*36 + q]
#define BW_THREADS 512
#define BW_WARPS   (BW_THREADS / 32)
#define BW_TASKS   (NTIME / 2)
#define BW_SMEM    ((32768 + BW_WARPS * 1152) * 4)

__global__ void __launch_bounds__(BW_THREADS, 1)
build_w_kernel(const float* __restrict__ T, const float* __restrict__ C)
{
    extern __shared__ float sm[];
    const int tid  = threadIdx.x;
    const int wid  = tid >> 5;
    const int lane = tid & 31;   // = p in the build

    // stage C: C[p][q][r] -> sm[((r*8 + q/4)*32 + p)*4 + (q&3)]
    for (int idx = tid; idx < 32768; idx += BW_THREADS) {
        int p = idx >> 10, q = (idx >> 5) & 31, r = idx & 31;
        sm[(((r * 8 + (q >> 2)) * 32 + p) << 2) + (q & 3)] = C[idx];
    }
    __syncthreads();

    float* Wtr = sm + 32768 + wid * 1152;

    while (true) {
        int task;
        if (lane == 0) task = atomicAdd(&g_ticket_w, 1);
        task = __shfl_sync(0xffffffffu, task, 0);
        if (task >= BW_TASKS) break;

        const int b0 = task * 2;
        const float tl0 = T[(size_t)b0 * 32 + lane];
        const float tl1 = T[(size_t)(b0 + 1) * 32 + lane];

        unsigned long long w0[16], w1[16];
        #pragma unroll
        for (int x = 0; x < 16; x++) { w0[x] = 0ULL; w1[x] = 0ULL; }

        #pragma unroll 4
        for (int r = 0; r < 32; r++) {
            float f0 = __shfl_sync(0xffffffffu, tl0, r);
            float f1 = __shfl_sync(0xffffffffu, tl1, r);
            unsigned long long tr0, tr1;
            PACK2(tr0, f0, f0);
            PACK2(tr1, f1, f1);
            const ulonglong2* crow = (const ulonglong2*)sm + (size_t)r * 256 + lane;
            #pragma unroll
            for (int q4 = 0; q4 < 8; q4++) {
                ulonglong2 cc = crow[q4 * 32];
                FMA2(w0[2*q4],     cc.x, tr0);
                FMA2(w0[2*q4 + 1], cc.y, tr0);
                FMA2(w1[2*q4],     cc.x, tr1);
                FMA2(w1[2*q4 + 1], cc.y, tr1);
            }
        }

        // per bucket: SMEM transpose then coalesced STG to g_W[b][p][q]
        #pragma unroll
        for (int g = 0; g < 2; g++) {
            float* wrow = Wtr + lane * 36;
            #pragma unroll
            for (int x = 0; x < 8; x++) {
                float a0, a1, a2, a3;
                UNPACK2(a0, a1, g ? w1[2*x]     : w0[2*x]);
                UNPACK2(a2, a3, g ? w1[2*x + 1] : w0[2*x + 1]);
                *(float4*)&wrow[4*x] = make_float4(a0, a1, a2, a3);
            }
            __syncwarp();
            float4* dst = (float4*)(g_W + (size_t)(b0 + g) * 1024);
            const int p = (lane >> 3);            // + 4c below
            const int q = (lane & 7) << 2;
            #pragma unroll
            for (int c = 0; c < 8; c++) {
                float4 f = *(const float4*)&Wtr[(c * 4 + p) * 36 + q];
                dst[c * 32 + lane] = f;           // coalesced 128B
            }
            __syncwarp();
        }
    }
}

// ============================ sample ============================
#define SP_THREADS 512
#define SP_WARPS   (SP_THREADS / 32)
#define SP_CTAS    (NUM_CTAS * 2)
#define SP_SMEM    (SP_WARPS * 1152 * 4)     // 73728 B -> 2 CTAs/SM

__global__ void __launch_bounds__(SP_THREADS, 2)
sample_kernel(const int* __restrict__ i_in, const int* __restrict__ j_in,
              const int* __restrict__ k_in,
              const float* __restrict__ U, const float* __restrict__ V,
              const float* __restrict__ T, const float* __restrict__ C,
              float* __restrict__ out)
{
    extern __shared__ float sm[];
    const uint32_t smb = smem_u32(sm);
    const int tid  = threadIdx.x;
    const int wid  = tid >> 5;
    const int lane = tid & 31;   // = sample within pass

    // overflow slow path (expected 0 iterations) — global C
    if (blockIdx.x == 0 && wid == 0 && g_ovf_cnt > 0) {
        int no = min(g_ovf_cnt, 4096);
        for (int o = 0; o < no; o++) {
            int idx = g_ovf[o];
            int iu = i_in[idx], ij = j_in[idx], ik = k_in[idx];
            float up = U[(size_t)iu * 32 + lane];     // lane = p here
            float sp = 0.f;
            for (int q = 0; q < 32; q++) {
                float vq = V[(size_t)ij * 32 + q];
                float acc = 0.f;
                #pragma unroll
                for (int r4 = 0; r4 < 8; r4++) {
                    float4 c4 = *(const float4*)&C[((size_t)(lane * 32 + q)) * 32 + r4 * 4];
                    float4 t4 = *(const float4*)&T[(size_t)ik * 32 + r4 * 4];
                    acc += c4.x * t4.x + c4.y * t4.y + c4.z * t4.z + c4.w * t4.w;
                }
                sp = fmaf(vq, acc, sp);
            }
            float val = up * sp;
            #pragma unroll
            for (int off = 16; off > 0; off >>= 1)
                val += __shfl_xor_sync(0xffffffffu, val, off);
            if (lane == 0) out[idx] = val;
        }
        if (lane == 0) g_ovf_cnt = 0;
    }

    float*         Wst   = sm + wid * 1152;
    const uint32_t Wst_a = smb + (uint32_t)wid * 1152u * 4u;

    while (true) {
        int b;
        if (lane == 0) b = atomicAdd(&g_ticket_s, 1);
        b = __shfl_sync(0xffffffffu, b, 0);
        if (b >= NTIME) break;

        int cnt;
        if (lane == 0) { cnt = g_counts[b]; g_counts[b] = 0; }   // reset for replay
        cnt = __shfl_sync(0xffffffffu, cnt, 0);
        if (cnt == 0) continue;
        cnt = min(cnt, CAP);

        // fetch W (coalesced) into per-warp staging, stride-36 rows
        {
            const float4* wb4 = (const float4*)(g_W + (size_t)b * 1024);
            const int p = (lane >> 3);
            const int q = (lane & 7) << 2;
            #pragma unroll
            for (int c = 0; c < 8; c++) {
                float4 f = wb4[c * 32 + lane];
                *(float4*)&Wst[(c * 4 + p) * 36 + q] = f;
            }
        }
        __syncwarp();

        // ---- sample passes (lane = sample) ----
        for (int base = 0; base < cnt; base += 32) {
            const int rem = cnt - base;
            int4 s4 = g_slot[b * CAP + base + min(lane, rem - 1)];
            const float* __restrict__ Urow = U + (size_t)s4.y * 32;
            const float* __restrict__ Vrow = V + (size_t)s4.z * 32;

            unsigned long long a2[16];
            #pragma unroll
            for (int x = 0; x < 16; x++) a2[x] = 0ULL;

            #pragma unroll 4
            for (int p4 = 0; p4 < 8; p4++) {
                float4 u4 = *(const float4*)&Urow[4 * p4];
                #pragma unroll
                for (int pp = 0; pp < 4; pp++) {
                    float up = (pp == 0) ? u4.x : (pp == 1) ? u4.y
                             : (pp == 2) ? u4.z : u4.w;
                    unsigned long long upk;
                    PACK2(upk, up, up);
                    const uint32_t row = Wst_a + (uint32_t)(4 * p4 + pp) * 144u;
                    #pragma unroll
                    for (int x = 0; x < 8; x++) {
                        unsigned long long c0, c1;
                        LDSV2U64(c0, c1, row + x * 16u);     // uniform broadcast
                        FMA2(a2[2 * x],     upk, c0);
                        FMA2(a2[2 * x + 1], upk, c1);
                    }
                }
            }

            unsigned long long acc = 0ULL;
            #pragma unroll
            for (int q4 = 0; q4 < 8; q4++) {
                float4 v4 = *(const float4*)&Vrow[4 * q4];
                unsigned long long v01, v23;
                PACK2(v01, v4.x, v4.y);
                PACK2(v23, v4.z, v4.w);
                FMA2(acc, a2[2 * q4],     v01);
                FMA2(acc, a2[2 * q4 + 1], v23);
            }
            float ylo, yhi;
            UNPACK2(ylo, yhi, acc);
            if (lane < rem) out[s4.x] = ylo + yhi;
        }
        __syncwarp();   // Wst reused next bucket
    }
}

// ============================ launch ============================
extern "C" void kernel_launch(void* const* d_in, const int* in_sizes, int n_in,
                              void* d_out, int out_size)
{
    const int*   i_in = (const int*)d_in[0];
    const int*   j_in = (const int*)d_in[1];
    const int*   k_in = (const int*)d_in[2];
    const float* U    = (const float*)d_in[3];
    const float* V    = (const float*)d_in[4];
    const float* T    = (const float*)d_in[5];
    const float* C    = (const float*)d_in[6];
    float*       out  = (float*)d_out;

    const int n = in_sizes[0];

    static bool configured = false;
    if (!configured) {
        cudaFuncSetAttribute(build_w_kernel,
                             cudaFuncAttributeMaxDynamicSharedMemorySize, BW_SMEM);
        cudaFuncSetAttribute(sample_kernel,
                             cudaFuncAttributeMaxDynamicSharedMemorySize, SP_SMEM);
        configured = true;
    }

    scatter_kernel<<<(n + 255) / 256, 256>>>(k_in, i_in, j_in, n);
    build_w_kernel<<<NUM_CTAS, BW_THREADS, BW_SMEM>>>(T, C);
    sample_kernel<<<SP_CTAS, SP_THREADS, SP_SMEM>>>(i_in, j_in, k_in,
                                                    U, V, T, C, out);
}

// round 16
// speedup vs baseline: 1.1099x; 1.1099x over previous
#include <cuda_runtime.h>
#include <cstdint>

// Tucker via time-bucketing, round 16: scatter + ONE persistent main kernel.
//   main: warp-task = 2 buckets. Build W0/W1 with packed f32x2 (C in SMEM,
//   float4-q layout). Then per bucket: stage W to per-warp SMEM (stride-36),
//   sample phase lane=sample with uniform LDS.128 W broadcasts (~26
//   issues/sample). w1 waits in 32 packed regs during bucket 0.

#define NTIME       5000
#define NTASKS      (NTIME / 2)
#define NUM_CTAS    148
#define CTA_THREADS 512
#define WARPS       (CTA_THREADS / 32)
#define CAP         96

// ---- device scratch (zero-init at load) ----
__device__ int4 g_slot[NTIME * CAP];     // (idx, iu, ij, 0)
__device__ int  g_counts[NTIME];
__device__ int  g_ovf[4096];
__device__ int  g_ovf_cnt;
__device__ int  g_ticket;

// ---- packed f32x2 helpers ----
#define PACK2(d, lo, hi) asm("mov.b64 %0, {%1, %2};" : "=l"(d) : "f"(lo), "f"(hi))
#define UNPACK2(lo, hi, s) asm("mov.b64 {%0, %1}, %2;" : "=f"(lo), "=f"(hi) : "l"(s))
#define FMA2(acc, a, b) asm("fma.rn.f32x2 %0, %1, %2, %0;" : "+l"(acc) : "l"(a), "l"(b))
#define LDSV2U64(d0, d1, addr) \
    asm volatile("ld.shared.v2.u64 {%0, %1}, [%2];" : "=l"(d0), "=l"(d1) : "r"(addr))

__device__ __forceinline__ uint32_t smem_u32(const void* p) {
    uint32_t a;
    asm("{ .reg .u64 t; cvta.to.shared.u64 t, %1; cvt.u32.u64 %0, t; }" : "=r"(a) : "l"(p));
    return a;
}

// ============================ scatter ============================
__global__ void scatter_kernel(const int* __restrict__ k_in,
                               const int* __restrict__ i_in,
                               const int* __restrict__ j_in, int n) {
    int x = blockIdx.x * blockDim.x + threadIdx.x;
    if (x == 0) g_ticket = 0;            // consumed by the later kernel
    if (x < n) {
        int k  = k_in[x];
        int iu = i_in[x];
        int ij = j_in[x];
        int pos = atomicAdd(&g_counts[k], 1);
        if (pos < CAP) {
            g_slot[k * CAP + pos] = make_int4(x, iu, ij, 0);
        } else {
            int o = atomicAdd(&g_ovf_cnt, 1);
            if (o < 4096) g_ovf[o] = x;
        }
    }
}

// ============================ main ============================
// SMEM (floats):
//   [0, 32768)    C as float4 q-quads: Cs4[(r*8 + q4)*32 + p] =
//                 {C[p][4q4..4q4+3][r]}   (16B/lane: conflict-free LDS.128)
//   per warp w:   32768 + wid*1152 : W staging Wst[p*36 + q] (16B aligned)
#define SM_W_OFF    32768
#define PW_FLOATS   1152
#define SMEM_FLOATS (SM_W_OFF + WARPS * PW_FLOATS)
#define SMEM_BYTES  (SMEM_FLOATS * 4)

__global__ void __launch_bounds__(CTA_THREADS, 1)
tucker_main(const int* __restrict__ i_in, const int* __restrict__ j_in,
            const int* __restrict__ k_in,
            const float* __restrict__ U, const float* __restrict__ V,
            const float* __restrict__ T, const float* __restrict__ C,
            float* __restrict__ out)
{
    extern __shared__ float sm[];
    const uint32_t smb = smem_u32(sm);
    const int tid  = threadIdx.x;
    const int wid  = tid >> 5;
    const int lane = tid & 31;

    // stage C: C[p][q][r] -> sm[((r*8 + q/4)*32 + p)*4 + (q&3)]
    for (int idx = tid; idx < 32768; idx += CTA_THREADS) {
        int p = idx >> 10, q = (idx >> 5) & 31, r = idx & 31;
        sm[(((r * 8 + (q >> 2)) * 32 + p) << 2) + (q & 3)] = C[idx];
    }
    __syncthreads();

    // overflow slow path (expected 0 iterations) — reads C from global
    if (blockIdx.x == 0 && wid == 0 && g_ovf_cnt > 0) {
        int no = min(g_ovf_cnt, 4096);
        for (int o = 0; o < no; o++) {
            int idx = g_ovf[o];
            int iu = i_in[idx], ij = j_in[idx], ik = k_in[idx];
            float up = U[(size_t)iu * 32 + lane];     // lane = p
            float sp = 0.f;
            for (int q = 0; q < 32; q++) {
                float vq = V[(size_t)ij * 32 + q];
                float acc = 0.f;
                #pragma unroll
                for (int r4 = 0; r4 < 8; r4++) {
                    float4 c4 = *(const float4*)&C[((size_t)(lane * 32 + q)) * 32 + r4 * 4];
                    float4 t4 = *(const float4*)&T[(size_t)ik * 32 + r4 * 4];
                    acc += c4.x * t4.x + c4.y * t4.y + c4.z * t4.z + c4.w * t4.w;
                }
                sp = fmaf(vq, acc, sp);
            }
            float val = up * sp;
            #pragma unroll
            for (int off = 16; off > 0; off >>= 1)
                val += __shfl_xor_sync(0xffffffffu, val, off);
            if (lane == 0) out[idx] = val;
        }
        if (lane == 0) g_ovf_cnt = 0;    // reset for next replay
    }

    float*         Wst   = sm + SM_W_OFF + wid * PW_FLOATS;
    const uint32_t Wst_a = smb + (uint32_t)(SM_W_OFF + wid * PW_FLOATS) * 4u;

    while (true) {
        int task;
        if (lane == 0) task = atomicAdd(&g_ticket, 1);
        task = __shfl_sync(0xffffffffu, task, 0);
        if (task >= NTASKS) break;

        const int b0 = task * 2;
        int cnt0, cnt1;
        if (lane == 0) { cnt0 = g_counts[b0];     g_counts[b0]     = 0; }
        if (lane == 1) { cnt1 = g_counts[b0 + 1]; g_counts[b0 + 1] = 0; }
        cnt0 = min(__shfl_sync(0xffffffffu, cnt0, 0), CAP);
        cnt1 = min(__shfl_sync(0xffffffffu, cnt1, 1), CAP);

        // ---- W build (lane = p), packed f32x2 over q-pairs, G = 2 ----
        unsigned long long w0[16], w1[16];
        {
            const float tl0 = T[(size_t)b0 * 32 + lane];        // lane = r
            const float tl1 = T[(size_t)(b0 + 1) * 32 + lane];
            #pragma unroll
            for (int x = 0; x < 16; x++) { w0[x] = 0ULL; w1[x] = 0ULL; }

            #pragma unroll 4
            for (int r = 0; r < 32; r++) {
                float f0 = __shfl_sync(0xffffffffu, tl0, r);
                float f1 = __shfl_sync(0xffffffffu, tl1, r);
                unsigned long long tr0, tr1;
                PACK2(tr0, f0, f0);
                PACK2(tr1, f1, f1);
                const ulonglong2* crow = (const ulonglong2*)sm + (size_t)r * 256 + lane;
                #pragma unroll
                for (int q4 = 0; q4 < 8; q4++) {
                    ulonglong2 cc = crow[q4 * 32];   // 16B/lane, conflict-free
                    FMA2(w0[2*q4],     cc.x, tr0);
                    FMA2(w0[2*q4 + 1], cc.y, tr0);
                    FMA2(w1[2*q4],     cc.x, tr1);
                    FMA2(w1[2*q4 + 1], cc.y, tr1);
                }
            }
        }

        // ---- per bucket: stage W, then lane=sample loop ----
        #pragma unroll
        for (int g = 0; g < 2; g++) {
            const int b   = b0 + g;
            const int cnt = g ? cnt1 : cnt0;

            // stage W_g: lane p owns row Wst[p*36 .. +32)
            {
                float* wrow = Wst + lane * 36;
                #pragma unroll
                for (int x = 0; x < 8; x++) {
                    float a0, a1, c0, c1;
                    UNPACK2(a0, a1, g ? w1[2*x]     : w0[2*x]);
                    UNPACK2(c0, c1, g ? w1[2*x + 1] : w0[2*x + 1]);
                    *(float4*)&wrow[4*x] = make_float4(a0, a1, c0, c1);
                }
            }
            __syncwarp();
            if (cnt == 0) continue;

            for (int base = 0; base < cnt; base += 32) {
                const int rem = cnt - base;
                int4 s4 = g_slot[b * CAP + base + min(lane, rem - 1)];
                const float* __restrict__ Urow = U + (size_t)s4.y * 32;
                const float* __restrict__ Vrow = V + (size_t)s4.z * 32;

                // a[q] (packed q-pairs) = sum_p u_p * W[p][q]
                unsigned long long a2[16];
                #pragma unroll
                for (int x = 0; x < 16; x++) a2[x] = 0ULL;

                #pragma unroll 4
                for (int p4 = 0; p4 < 8; p4++) {
                    float4 u4 = *(const float4*)&Urow[4 * p4];   // per-lane gather
                    #pragma unroll
                    for (int pp = 0; pp < 4; pp++) {
                        float up = (pp == 0) ? u4.x : (pp == 1) ? u4.y
                                 : (pp == 2) ? u4.z : u4.w;
                        unsigned long long upk;
                        PACK2(upk, up, up);
                        const uint32_t row = Wst_a + (uint32_t)(4 * p4 + pp) * 144u;
                        #pragma unroll
                        for (int x = 0; x < 8; x++) {
                            unsigned long long c0, c1;
                            LDSV2U64(c0, c1, row + x * 16u);     // uniform broadcast
                            FMA2(a2[2 * x],     upk, c0);
                            FMA2(a2[2 * x + 1], upk, c1);
                        }
                    }
                }

                // y = sum_q a_q * v_q
                unsigned long long acc = 0ULL;
                #pragma unroll
                for (int q4 = 0; q4 < 8; q4++) {
                    float4 v4 = *(const float4*)&Vrow[4 * q4];
                    unsigned long long v01, v23;
                    PACK2(v01, v4.x, v4.y);
                    PACK2(v23, v4.z, v4.w);
                    FMA2(acc, a2[2 * q4],     v01);
                    FMA2(acc, a2[2 * q4 + 1], v23);
                }
                float ylo, yhi;
                UNPACK2(ylo, yhi, acc);
                if (lane < rem) out[s4.x] = ylo + yhi;
            }
            __syncwarp();   // Wst reused for next bucket / task
        }
    }
}

extern "C" void kernel_launch(void* const* d_in, const int* in_sizes, int n_in,
                              void* d_out, int out_size)
{
    const int*   i_in = (const int*)d_in[0];
    const int*   j_in = (const int*)d_in[1];
    const int*   k_in = (const int*)d_in[2];
    const float* U    = (const float*)d_in[3];
    const float* V    = (const float*)d_in[4];
    const float* T    = (const float*)d_in[5];
    const float* C    = (const float*)d_in[6];
    float*       out  = (float*)d_out;

    const int n = in_sizes[0];

    static bool configured = false;
    if (!configured) {
        cudaFuncSetAttribute(tucker_main,
                             cudaFuncAttributeMaxDynamicSharedMemorySize,
                             SMEM_BYTES);
        configured = true;
    }

    scatter_kernel<<<(n + 255) / 256, 256>>>(k_in, i_in, j_in, n);
    tucker_main<<<NUM_CTAS, CTA_THREADS, SMEM_BYTES>>>(i_in, j_in, k_in,
                                                       U, V, T, C, out);
}